// round 6
// baseline (speedup 1.0000x reference)
#include <cuda_runtime.h>
#include <cstdint>

// SAR-ADC 4-bit successive approximation quantizer.
// x: [500000, 24] f32 (12M elems), W: [10] f32.
// d_out: q [12M] f32 followed by Q [12M][4] f32.
//
// v4: pair-per-lane + 256-bit stores + streaming (.cs) cache policy.
//   Warp owns 512 consecutive elements (8 pairs/thread). Thread t, step k
//   (0..7) handles the pair e = warpBase + 64*k + 2*t:
//     x  : ld.global.nc.cs.v2  (dense 256B/warp-instr, evict-first)
//     q  : st.global.cs.v2     (dense 256B, evict-first)
//     Q  : st.global.cs.v8     (dense 1KB,  evict-first)  [sm_100+]
//   All streams are touch-once; .cs keeps them from churning the 126MB L2
//   and lets writeback drain early/smoothly (write-dominant 1:5 mix).
//
// Compute: compare-direct thresholds (exactly equivalent to
//   sign(x - t + 1e-30): operands are O(0.1) so |x-t| is 0 or >= ~7e-9
//   >> 1e-30, and equality gives sign(+1e-30) = +1 = (x >= t)).

#define VRf    0.1125f
#define VREFf  0.1125f

struct QR { float s0, s1, s2, s3, q; };

__device__ __forceinline__ QR quant1(
    float xx,
    float T3, float T2_0, float T2_1,
    float c1, float c1a, float c1b,
    float c0, float c0a, float c0b, float c0c)
{
    const bool  p3 = (xx >= T3);
    const float b3 = p3 ? 1.0f : 0.0f;
    const float t2 = p3 ? T2_1 : T2_0;

    const bool  p2 = (xx >= t2);
    const float b2 = p2 ? 1.0f : 0.0f;
    const float t1 = fmaf(b2, c1a, fmaf(b3, c1b, c1));

    const bool  p1 = (xx >= t1);
    const float b1 = p1 ? 1.0f : 0.0f;
    const float t0 = fmaf(b1, c0a, fmaf(b2, c0b, fmaf(b3, c0c, c0)));

    const bool  p0 = (xx >= t0);
    const float b0 = p0 ? 1.0f : 0.0f;

    QR r;
    r.s0 = p0 ? 1.0f : -1.0f;
    r.s1 = p1 ? 1.0f : -1.0f;
    r.s2 = p2 ? 1.0f : -1.0f;
    r.s3 = p3 ? 1.0f : -1.0f;
    float f = fmaf(b1, 2.0f, b0);
    f = fmaf(b2, 4.0f, f);
    f = fmaf(b3, 8.0f, f);
    r.q = f * VRf;
    return r;
}

__device__ __forceinline__ float2 ldg_cs_f2(const float* p) {
    float2 v;
    asm volatile("ld.global.nc.cs.v2.f32 {%0, %1}, [%2];"
                 : "=f"(v.x), "=f"(v.y) : "l"(p));
    return v;
}

__device__ __forceinline__ void stg_cs_f2(float* p, float a, float b) {
    asm volatile("st.global.cs.v2.f32 [%0], {%1, %2};"
                 :: "l"(p), "f"(a), "f"(b) : "memory");
}

__device__ __forceinline__ void stg_cs_f8(float* p,
    float a0, float a1, float a2, float a3,
    float a4, float a5, float a6, float a7)
{
    asm volatile(
        "st.global.cs.v8.f32 [%0], {%1, %2, %3, %4, %5, %6, %7, %8};"
        :: "l"(p),
           "f"(a0), "f"(a1), "f"(a2), "f"(a3),
           "f"(a4), "f"(a5), "f"(a6), "f"(a7)
        : "memory");
}

__global__ __launch_bounds__(256) void sar_adc_kernel(
    const float* __restrict__ x,
    const float* __restrict__ W,
    float* __restrict__ q_out,   // 12M floats
    float* __restrict__ Q_out,   // 48M floats
    int n)                       // total elements
{
    const int tid      = blockIdx.x * blockDim.x + threadIdx.x;
    const int warp_id  = tid >> 5;
    const int lane     = tid & 31;
    const int warpBase = warp_id << 9;        // 512 elements per warp

    if (warpBase >= n) return;

    // Uniform weight loads (L1 broadcast).
    const float w0 = __ldg(&W[0]), w1 = __ldg(&W[1]), w2 = __ldg(&W[2]);
    const float w3 = __ldg(&W[3]), w4 = __ldg(&W[4]), w5 = __ldg(&W[5]);
    const float w6 = __ldg(&W[6]), w7 = __ldg(&W[7]), w8 = __ldg(&W[8]);
    const float w9 = __ldg(&W[9]);

    const float T3   = w9 * VREFf;
    const float T2_0 = w8 * VREFf;
    const float T2_1 = T2_0 + w7 * VRf;
    const float c1   = w6 * VREFf, c1a = w5 * VRf, c1b = w4 * VRf;
    const float c0   = w3 * VREFf, c0a = w2 * VRf, c0b = w1 * VRf, c0c = w0 * VRf;

    const int e0 = warpBase + 2 * lane;

    // Tail-safe full-warp check: n is a multiple of 512 in this problem,
    // but guard each half-batch anyway.
#pragma unroll
    for (int h = 0; h < 2; ++h) {
        const int hbase = e0 + h * 256;
        if (warpBase + h * 256 >= n) return;

        // Front-batch 4 pair loads (MLP=4 per half-batch).
        float2 xv[4];
#pragma unroll
        for (int k = 0; k < 4; ++k)
            xv[k] = ldg_cs_f2(x + hbase + 64 * k);

#pragma unroll
        for (int k = 0; k < 4; ++k) {
            const int e = hbase + 64 * k;

            const QR a = quant1(xv[k].x, T3, T2_0, T2_1, c1, c1a, c1b, c0, c0a, c0b, c0c);
            const QR b = quant1(xv[k].y, T3, T2_0, T2_1, c1, c1a, c1b, c0, c0a, c0b, c0c);

            stg_cs_f2(q_out + e, a.q, b.q);
            stg_cs_f8(Q_out + (size_t)e * 4,
                      a.s0, a.s1, a.s2, a.s3,
                      b.s0, b.s1, b.s2, b.s3);
        }
    }
}

extern "C" void kernel_launch(void* const* d_in, const int* in_sizes, int n_in,
                              void* d_out, int out_size) {
    const float* x = (const float*)d_in[0];
    const float* W = (const float*)d_in[1];

    const int n = in_sizes[0];            // 12,000,000 elements
    float* q_out = (float*)d_out;
    float* Q_out = (float*)d_out + n;

    const int threads = 256;
    const int elems_per_block = threads * 16;   // 4096 (512 per warp)
    const int blocks = (n + elems_per_block - 1) / elems_per_block;
    sar_adc_kernel<<<blocks, threads>>>(x, W, q_out, Q_out, n);
}

// round 7
// speedup vs baseline: 1.1993x; 1.1993x over previous
#include <cuda_runtime.h>
#include <cstdint>

// SAR-ADC 4-bit successive approximation quantizer.
// x: [500000, 24] f32 (12M elems), W: [10] f32.
// d_out: q [12M] f32 followed by Q [12M][4] f32.
//
// v5: revert of the .cs experiment (R6 regression: .cs stores inflated
// L1tex wavefronts, L1 73% / DRAM 51%). Back to plain cache ops +
// pair-per-lane + STG.256, with 2 pairs per thread (128 elems/warp,
// grid ~11719) for maximal warp-level parallelism / smoothest waves.
//
//   Warp owns 128 consecutive elements. Thread t, step k (0..1) handles
//   the pair e = warpBase + 64*k + 2*t:
//     x  : LDG.64   (dense 256B per warp-instr)
//     q  : STG.64   (dense 256B)
//     Q  : STG.256  (dense 1KB)   [sm_100+ st.global.v8.f32]
//
// Compute: compare-direct thresholds — exactly equivalent to
//   sign(x - t + 1e-30): operands are O(0.1) so |x-t| is 0 or >= ~7e-9
//   >> 1e-30, and equality gives sign(+1e-30) = +1 = (x >= t).

#define VRf    0.1125f
#define VREFf  0.1125f

struct QR { float s0, s1, s2, s3, q; };

__device__ __forceinline__ QR quant1(
    float xx,
    float T3, float T2_0, float T2_1,
    float c1, float c1a, float c1b,
    float c0, float c0a, float c0b, float c0c)
{
    const bool  p3 = (xx >= T3);
    const float b3 = p3 ? 1.0f : 0.0f;
    const float t2 = p3 ? T2_1 : T2_0;

    const bool  p2 = (xx >= t2);
    const float b2 = p2 ? 1.0f : 0.0f;
    const float t1 = fmaf(b2, c1a, fmaf(b3, c1b, c1));

    const bool  p1 = (xx >= t1);
    const float b1 = p1 ? 1.0f : 0.0f;
    const float t0 = fmaf(b1, c0a, fmaf(b2, c0b, fmaf(b3, c0c, c0)));

    const bool  p0 = (xx >= t0);
    const float b0 = p0 ? 1.0f : 0.0f;

    QR r;
    r.s0 = p0 ? 1.0f : -1.0f;
    r.s1 = p1 ? 1.0f : -1.0f;
    r.s2 = p2 ? 1.0f : -1.0f;
    r.s3 = p3 ? 1.0f : -1.0f;
    float f = fmaf(b1, 2.0f, b0);
    f = fmaf(b2, 4.0f, f);
    f = fmaf(b3, 8.0f, f);
    r.q = f * VRf;
    return r;
}

__device__ __forceinline__ void stg256(float* p,
    float a0, float a1, float a2, float a3,
    float a4, float a5, float a6, float a7)
{
    asm volatile(
        "st.global.v8.f32 [%0], {%1, %2, %3, %4, %5, %6, %7, %8};"
        :: "l"(p),
           "f"(a0), "f"(a1), "f"(a2), "f"(a3),
           "f"(a4), "f"(a5), "f"(a6), "f"(a7)
        : "memory");
}

__global__ __launch_bounds__(256) void sar_adc_kernel(
    const float* __restrict__ x,
    const float* __restrict__ W,
    float* __restrict__ q_out,   // 12M floats
    float* __restrict__ Q_out,   // 48M floats
    int n)                       // total elements; multiple of 128
{
    const int tid      = blockIdx.x * blockDim.x + threadIdx.x;
    const int warp_id  = tid >> 5;
    const int lane     = tid & 31;
    const int warpBase = warp_id << 7;        // 128 elements per warp

    if (warpBase >= n) return;                // n % 128 == 0: active warps full

    // Uniform weight loads (L1 broadcast).
    const float w0 = __ldg(&W[0]), w1 = __ldg(&W[1]), w2 = __ldg(&W[2]);
    const float w3 = __ldg(&W[3]), w4 = __ldg(&W[4]), w5 = __ldg(&W[5]);
    const float w6 = __ldg(&W[6]), w7 = __ldg(&W[7]), w8 = __ldg(&W[8]);
    const float w9 = __ldg(&W[9]);

    const float T3   = w9 * VREFf;
    const float T2_0 = w8 * VREFf;
    const float T2_1 = T2_0 + w7 * VRf;
    const float c1   = w6 * VREFf, c1a = w5 * VRf, c1b = w4 * VRf;
    const float c0   = w3 * VREFf, c0a = w2 * VRf, c0b = w1 * VRf, c0c = w0 * VRf;

    const int e0 = warpBase + 2 * lane;

    // Front-batch both pair loads (MLP=2, plenty of warps for latency hiding).
    float2 xv[2];
#pragma unroll
    for (int k = 0; k < 2; ++k)
        xv[k] = *reinterpret_cast<const float2*>(x + e0 + 64 * k);

#pragma unroll
    for (int k = 0; k < 2; ++k) {
        const int e = e0 + 64 * k;

        const QR a = quant1(xv[k].x, T3, T2_0, T2_1, c1, c1a, c1b, c0, c0a, c0b, c0c);
        const QR b = quant1(xv[k].y, T3, T2_0, T2_1, c1, c1a, c1b, c0, c0a, c0b, c0c);

        *reinterpret_cast<float2*>(q_out + e) = make_float2(a.q, b.q);

        stg256(Q_out + (size_t)e * 4,
               a.s0, a.s1, a.s2, a.s3,
               b.s0, b.s1, b.s2, b.s3);
    }
}

extern "C" void kernel_launch(void* const* d_in, const int* in_sizes, int n_in,
                              void* d_out, int out_size) {
    const float* x = (const float*)d_in[0];
    const float* W = (const float*)d_in[1];

    const int n = in_sizes[0];            // 12,000,000 elements (multiple of 128)
    float* q_out = (float*)d_out;
    float* Q_out = (float*)d_out + n;

    const int threads = 256;
    const int elems_per_block = threads * 4;   // 1024 (128 per warp)
    const int blocks = (n + elems_per_block - 1) / elems_per_block;
    sar_adc_kernel<<<blocks, threads>>>(x, W, q_out, Q_out, n);
}